// round 9
// baseline (speedup 1.0000x reference)
#include <cuda_runtime.h>
#include <cuda_fp16.h>
#include <cstdint>
#include <math.h>

// ---------------- problem dims (fixed by dataset) ----------------
#define Bx 1024
#define TT 256
#define II 64
#define UU 1024
#define NN 4096            // 4*UU gate columns (interleaved n' = 4u+g)
#define KK (II + UU)       // 1088 (warmup), decode K = UU = 1024
// ---------------- tiling ----------------
#define MT  128            // M tile (batch rows per CTA)
#define NTL 256            // N tile (gate cols per CTA) = 64 units
#define KC  64             // K chunk per stage (128B rows, SW128)
#define NTHR 512           // 16 warps, warp grid 2(M) x 8(N), warp tile 64x32
#define ZS_STRIDE 260      // z SMEM row stride (floats)

typedef __half f16;
typedef unsigned int u32;

// ---------------- device state (no allocation allowed) ----------------
__device__ f16 g_Wt_hi[NN * KK];        // warmup W^T, gate-interleaved, K-major
__device__ f16 g_Wt_lo[NN * KK];
__device__ f16 g_W2_hi[NN * UU];        // decode W'^T = (Wr + Wd@Wk)^T interleaved
__device__ f16 g_W2_lo[NN * UU];
__device__ float g_b2[NN];              // b' = b + bd@Wk (gate-major)
__device__ f16 g_x[Bx * TT * II];       // inputs, fp16
__device__ f16 g_h[2 * Bx * UU];        // double-buffered hidden state, fp16
__device__ float g_c[Bx * UU];

// ---------------- helpers ----------------
__device__ __forceinline__ u32 smem_u32(const void* p) {
    u32 a;
    asm("{ .reg .u64 t; cvta.to.shared.u64 t, %1; cvt.u32.u64 %0, t; }" : "=r"(a) : "l"(p));
    return a;
}
#define SWZ(o) ((o) ^ ((((u32)(o)) >> 3) & 0x70))

__device__ __forceinline__ void cp16(u32 dst, const void* src) {
    asm volatile("cp.async.cg.shared.global [%0], [%1], 16;\n" :: "r"(dst), "l"(src) : "memory");
}
__device__ __forceinline__ void cp_commit() {
    asm volatile("cp.async.commit_group;\n" ::: "memory");
}
template<int N> __device__ __forceinline__ void cp_wait() {
    asm volatile("cp.async.wait_group %0;\n" :: "n"(N) : "memory");
}
__device__ __forceinline__ void ldsm4(u32* r, u32 addr) {
    asm volatile("ldmatrix.sync.aligned.m8n8.x4.shared.b16 {%0,%1,%2,%3}, [%4];"
                 : "=r"(r[0]), "=r"(r[1]), "=r"(r[2]), "=r"(r[3]) : "r"(addr));
}
__device__ __forceinline__ void mma16816(float* c, const u32* a, const u32* b) {
    asm volatile("mma.sync.aligned.m16n8k16.row.col.f32.f16.f16.f32 "
                 "{%0,%1,%2,%3}, {%4,%5,%6,%7}, {%8,%9}, {%0,%1,%2,%3};"
                 : "+f"(c[0]), "+f"(c[1]), "+f"(c[2]), "+f"(c[3])
                 : "r"(a[0]), "r"(a[1]), "r"(a[2]), "r"(a[3]), "r"(b[0]), "r"(b[1]));
}
// fast sigmoid/tanh: MUFU EX2 + MUFU RCP (error ~ulp scale, negligible here)
__device__ __forceinline__ float sigm(float z) {
    return __fdividef(1.0f, 1.0f + __expf(-z));
}
__device__ __forceinline__ float tanhfast(float z) {
    return __fdividef(2.0f, 1.0f + __expf(-2.0f * z)) - 1.0f;
}

// ---------------- prep kernels (once per launch) ----------------
__global__ void prep_weights(const float* __restrict__ Wk, const float* __restrict__ Wr) {
    const int np = blockIdx.x;               // n' = 4u+g
    const int u = np >> 2, g = np & 3;
    const int col = g * UU + u;
    for (int k = threadIdx.x; k < KK; k += blockDim.x) {
        float w = (k < II) ? Wk[(size_t)k * NN + col] : Wr[(size_t)(k - II) * NN + col];
        f16 hi = __float2half_rn(w);
        g_Wt_hi[(size_t)np * KK + k] = hi;
        g_Wt_lo[(size_t)np * KK + k] = __float2half_rn(w - __half2float(hi));
    }
}
// Decode W'^T = (Wr + Wd@Wk)^T and b' = b + bd@Wk.
__global__ void prep_w2(const float* __restrict__ Wk, const float* __restrict__ Wr,
                        const float* __restrict__ Wd, const float* __restrict__ b,
                        const float* __restrict__ bd) {
    __shared__ float wkcol[II];
    const int np = blockIdx.x;
    const int u = np >> 2, g = np & 3;
    const int col = g * UU + u;
    if (threadIdx.x < II) wkcol[threadIdx.x] = Wk[(size_t)threadIdx.x * NN + col];
    __syncthreads();
    for (int k = threadIdx.x; k < UU; k += blockDim.x) {
        float w = Wr[(size_t)k * NN + col];
        #pragma unroll 16
        for (int i = 0; i < II; i++) w += Wd[(size_t)k * II + i] * wkcol[i];
        f16 hi = __float2half_rn(w);
        g_W2_hi[(size_t)np * UU + k] = hi;
        g_W2_lo[(size_t)np * UU + k] = __float2half_rn(w - __half2float(hi));
    }
    if (threadIdx.x == 0) {
        float bb = b[col];
        for (int i = 0; i < II; i++) bb += bd[i] * wkcol[i];
        g_b2[col] = bb;
    }
}
__global__ void prep_inputs(const float* __restrict__ x) {
    size_t i = (size_t)blockIdx.x * blockDim.x + threadIdx.x;
    if (i >= (size_t)Bx * TT * II) return;
    g_x[i] = __float2half_rn(x[i]);
}

// ---------------- LSTM step via mma.sync (HMMA), fp16 2-term ----------------
// grid (16|17, 8). 512 thr = 16 warps, warp grid 2(M) x 8(N), warp tile 64x32.
// z = A*Bh + A*Bl (A fp16, B split fp16 hi/lo), fp32 accum.
// CTAs with blockIdx.x == 16 (decode only) emit out[out_s] from the INPUT h
// (already final) — rides on otherwise-idle SMs, replacing a separate kernel.
__global__ __launch_bounds__(NTHR, 1)
void lstm_step_mma(const f16* __restrict__ xp, int x_ld, int first_is_x,
                   const f16* __restrict__ hp,
                   const f16* __restrict__ wth, const f16* __restrict__ wtl, int wt_k,
                   f16* __restrict__ op,
                   float* __restrict__ c, const float* __restrict__ bias, int nstg,
                   const float* __restrict__ Wd, const float* __restrict__ bd,
                   const int* __restrict__ oidx, int n_idx,
                   float* __restrict__ out, int out_s, int S)
{
    extern __shared__ char dynsmem[];
    __shared__ float s_bias[NTL];

    const int tid  = threadIdx.x;
    const int wid  = tid >> 5;
    const int lane = tid & 31;
    const int ni = blockIdx.x, mi = blockIdx.y;
    const int b0 = mi * MT;

    // ---- output-head CTAs (decode only) ----
    if (ni == 16) {
        const int o0 = oidx[0];
        const int o1 = (n_idx > 1) ? oidx[1] : 0;
        #pragma unroll 1
        for (int rep = 0; rep < 8; rep++) {
            const int b = b0 + wid * 8 + rep;
            float a0 = 0.0f, a1 = 0.0f;
            #pragma unroll 4
            for (int i = 0; i < UU / 32; i++) {
                int u = lane + i * 32;
                float hv = __half2float(hp[(size_t)b * UU + u]);
                a0 += hv * Wd[(size_t)u * II + o0];
                a1 += hv * Wd[(size_t)u * II + o1];
            }
            #pragma unroll
            for (int off = 16; off > 0; off >>= 1) {
                a0 += __shfl_down_sync(0xFFFFFFFFu, a0, off);
                a1 += __shfl_down_sync(0xFFFFFFFFu, a1, off);
            }
            if (lane == 0) {
                out[((size_t)b * S + out_s) * n_idx + 0] = a0 + bd[o0];
                if (n_idx > 1) out[((size_t)b * S + out_s) * n_idx + 1] = a1 + bd[o1];
            }
        }
        return;
    }

    char* smg = dynsmem + ((1024 - ((uintptr_t)dynsmem & 1023)) & 1023);
    const u32 base = smem_u32(smg);
    const int n0 = ni * NTL;
    const int u0 = ni * 64;
    const int wm = (wid & 1) * 64;           // warp M offset (2 x 64 = 128)
    const int wn = (wid >> 1) * 32;          // warp N offset (8 x 32 = 256)

    // stage buffers: per buf 80KB = A(16K) Bh(32K) Bl(32K)
    #define AT(bf)    (base + (bf) * 81920u)
    #define BT(bf, p) (base + (bf) * 81920u + 16384u + (p) * 32768u)

    if (tid < NTL) s_bias[tid] = bias[(tid & 3) * UU + u0 + (tid >> 2)];

    float acc[4][4][4];
    #pragma unroll
    for (int m = 0; m < 4; m++)
        #pragma unroll
        for (int n = 0; n < 4; n++)
            #pragma unroll
            for (int q = 0; q < 4; q++) acc[m][n][q] = 0.0f;

    auto issue_loads = [&](int s, int buf) {
        const int kg = s * KC;
        const f16* A; int lda, ka;
        if (first_is_x && s == 0) { A = xp; lda = x_ld; ka = 0; }
        else { A = hp; lda = UU; ka = kg - (first_is_x ? II : 0); }
        #pragma unroll
        for (int i = 0; i < 2; i++) {            // A: 1024 chunks / 512 thr
            int idx = tid + i * NTHR;
            int row = idx >> 3, q = idx & 7;
            cp16(AT(buf) + SWZ(row * 128 + q * 16),
                 A + (size_t)(b0 + row) * lda + ka + q * 8);
        }
        #pragma unroll
        for (int p = 0; p < 2; p++) {
            const f16* src = p ? wtl : wth;
            #pragma unroll
            for (int i = 0; i < 4; i++) {        // B: 2048 chunks per part / 512
                int idx = tid + i * NTHR;
                int row = idx >> 3, q = idx & 7;
                cp16(BT(buf, p) + SWZ(row * 128 + q * 16),
                     src + (size_t)(n0 + row) * wt_k + kg + q * 8);
            }
        }
        cp_commit();
    };

    issue_loads(0, 0);

    for (int t = 0; t < nstg; t++) {
        const int buf = t & 1;
        if (t + 1 < nstg) { issue_loads(t + 1, buf ^ 1); cp_wait<1>(); }
        else              { cp_wait<0>(); }
        __syncthreads();

        #pragma unroll
        for (int kk = 0; kk < 4; kk++) {
            // A: 4 x m16k16 fragments (warp M = 64)
            u32 ah[4][4];
            #pragma unroll
            for (int m = 0; m < 4; m++) {
                int row = wm + m * 16 + (lane & 15);
                ldsm4(ah[m], AT(buf) + SWZ(row * 128 + kk * 32 + (lane >> 4) * 16));
            }
            // B-hi: 4 x n8k16 fragments (warp N = 32, pairs via x4)
            u32 bh[4][2];
            #pragma unroll
            for (int hf = 0; hf < 2; hf++) {
                int n = wn + hf * 16 + (lane >> 4) * 8 + (lane & 7);
                u32 r[4];
                ldsm4(r, BT(buf, 0) + SWZ(n * 128 + kk * 32 + ((lane >> 3) & 1) * 16));
                bh[hf * 2][0] = r[0];     bh[hf * 2][1] = r[1];
                bh[hf * 2 + 1][0] = r[2]; bh[hf * 2 + 1][1] = r[3];
            }
            #pragma unroll
            for (int m = 0; m < 4; m++)
                #pragma unroll
                for (int n = 0; n < 4; n++) mma16816(acc[m][n], ah[m], bh[n]);

            // A * B-lo (streamed)
            #pragma unroll
            for (int hf = 0; hf < 2; hf++) {
                int n = wn + hf * 16 + (lane >> 4) * 8 + (lane & 7);
                u32 r[4];
                ldsm4(r, BT(buf, 1) + SWZ(n * 128 + kk * 32 + ((lane >> 3) & 1) * 16));
                u32 b0f[2] = { r[0], r[1] }, b1f[2] = { r[2], r[3] };
                #pragma unroll
                for (int m = 0; m < 4; m++) {
                    mma16816(acc[m][hf * 2],     ah[m], b0f);
                    mma16816(acc[m][hf * 2 + 1], ah[m], b1f);
                }
            }
        }
        __syncthreads();
    }

    // ---------------- epilogue: accums -> SMEM -> gate math -> c,h ----------------
    float* zs = (float*)smg;   // 128 x ZS_STRIDE fp32, reuses stage bufs
    #pragma unroll
    for (int m = 0; m < 4; m++) {
        int row = wm + m * 16 + (lane >> 2);
        #pragma unroll
        for (int n = 0; n < 4; n++) {
            int col = wn + n * 8 + (lane & 3) * 2;
            *(float2*)&zs[row * ZS_STRIDE + col]       = make_float2(acc[m][n][0], acc[m][n][1]);
            *(float2*)&zs[(row + 8) * ZS_STRIDE + col] = make_float2(acc[m][n][2], acc[m][n][3]);
        }
    }
    __syncthreads();

    #pragma unroll 1
    for (int it = 0; it < (MT * 64) / NTHR; it++) {    // 16 iterations
        int idx = tid + it * NTHR;
        int row = idx >> 6;
        int ul  = idx & 63;
        float4 z = *(const float4*)&zs[row * ZS_STRIDE + 4 * ul];
        float zi = z.x + s_bias[4 * ul + 0];
        float zf = z.y + s_bias[4 * ul + 1];
        float zg = z.z + s_bias[4 * ul + 2];
        float zo = z.w + s_bias[4 * ul + 3];

        const size_t gidx = (size_t)(b0 + row) * UU + u0 + ul;
        float cv = c[gidx];
        float cn = sigm(zf) * cv + sigm(zi) * tanhfast(zg);
        c[gidx] = cn;
        op[gidx] = __float2half_rn(sigm(zo) * tanhfast(cn));
    }
    #undef AT
    #undef BT
}

// ---------------- standalone output kernel (used once, for the final step) ----
__global__ __launch_bounds__(256) void out_kernel(
    const f16* __restrict__ hp,
    const float* __restrict__ Wd, const float* __restrict__ bd,
    const int* __restrict__ oidx, int n_idx,
    float* __restrict__ out, int s, int S)
{
    const int wid  = threadIdx.x >> 5;
    const int lane = threadIdx.x & 31;
    const int b = blockIdx.x * 8 + wid;

    float a0 = 0.0f, a1 = 0.0f;
    const int o0 = oidx[0];
    const int o1 = (n_idx > 1) ? oidx[1] : 0;
    #pragma unroll 4
    for (int i = 0; i < UU / 32; i++) {
        int u = lane + i * 32;
        float hv = __half2float(hp[(size_t)b * UU + u]);
        a0 += hv * Wd[(size_t)u * II + o0];
        a1 += hv * Wd[(size_t)u * II + o1];
    }
    #pragma unroll
    for (int off = 16; off > 0; off >>= 1) {
        a0 += __shfl_down_sync(0xFFFFFFFFu, a0, off);
        a1 += __shfl_down_sync(0xFFFFFFFFu, a1, off);
    }
    if (lane == 0) {
        out[((size_t)b * S + s) * n_idx + 0] = a0 + bd[o0];
        if (n_idx > 1) out[((size_t)b * S + s) * n_idx + 1] = a1 + bd[o1];
    }
}

// ---------------- host driver ----------------
extern "C" void kernel_launch(void* const* d_in, const int* in_sizes, int n_in,
                              void* d_out, int out_size)
{
    const float* inputs = (const float*)d_in[0];
    const float* Wk     = (const float*)d_in[1];
    const float* Wr     = (const float*)d_in[2];
    const float* bias   = (const float*)d_in[3];
    const float* Wd     = (const float*)d_in[4];
    const float* bd     = (const float*)d_in[5];
    const int*   oidx   = (const int*)d_in[6];
    float*       out    = (float*)d_out;

    const int n_idx = in_sizes[6];
    const int S     = out_size / (Bx * n_idx);

    f16 *xp, *hb, *wth, *wtl, *w2h, *w2l;
    float *cb, *b2;
    cudaGetSymbolAddress((void**)&xp, g_x);
    cudaGetSymbolAddress((void**)&hb, g_h);
    cudaGetSymbolAddress((void**)&cb, g_c);
    cudaGetSymbolAddress((void**)&wth, g_Wt_hi);
    cudaGetSymbolAddress((void**)&wtl, g_Wt_lo);
    cudaGetSymbolAddress((void**)&w2h, g_W2_hi);
    cudaGetSymbolAddress((void**)&w2l, g_W2_lo);
    cudaGetSymbolAddress((void**)&b2, g_b2);

    const int dyn_smem = 2 * 81920 + 1024;   // 164864 B
    cudaFuncSetAttribute(lstm_step_mma, cudaFuncAttributeMaxDynamicSharedMemorySize, dyn_smem);

    // one-time-per-launch prep
    prep_weights<<<NN, 256>>>(Wk, Wr);
    prep_w2<<<NN, 256>>>(Wk, Wr, Wd, bias, bd);
    prep_inputs<<<(Bx * TT * II) / 256, 256>>>(inputs);
    cudaMemsetAsync(hb, 0, sizeof(f16) * Bx * UU);   // zero buffer 0 only
    cudaMemsetAsync(cb, 0, sizeof(float) * Bx * UU);

    int cur = 0;

    // warmup: 256 steps, K = 1088 (x chunk + h), grid (16,8)
    const dim3 grid_w(16, Bx / MT);
    for (int t = 0; t < TT; t++) {
        lstm_step_mma<<<grid_w, NTHR, dyn_smem>>>(
            xp + (size_t)t * II, TT * II, 1,
            hb + (size_t)cur * Bx * UU,
            wth, wtl, KK,
            hb + (size_t)(cur ^ 1) * Bx * UU,
            cb, bias, KK / KC,
            Wd, bd, oidx, n_idx, out, -1, S);
        cur ^= 1;
    }

    // decode: folded weights W' = Wr + Wd@Wk, K = 1024, grid (17,8);
    // the 17th CTA column emits out[s-1] from the input h (already final).
    const dim3 grid_d(17, Bx / MT);
    for (int s = 1; s < S; s++) {
        lstm_step_mma<<<grid_d, NTHR, dyn_smem>>>(
            (const f16*)0, 0, 0,
            hb + (size_t)cur * Bx * UU,
            w2h, w2l, UU,
            hb + (size_t)(cur ^ 1) * Bx * UU,
            cb, b2, UU / KC,
            Wd, bd, oidx, n_idx, out, s - 1, S);
        cur ^= 1;
    }

    // final step's output
    out_kernel<<<Bx / 8, 256>>>(hb + (size_t)cur * Bx * UU, Wd, bd, oidx, n_idx,
                                out, S - 1, S);
}

// round 10
// speedup vs baseline: 1.3249x; 1.3249x over previous
#include <cuda_runtime.h>
#include <cuda_fp16.h>
#include <cstdint>
#include <math.h>

// ---------------- problem dims (fixed by dataset) ----------------
#define Bx 1024
#define TT 256
#define II 64
#define UU 1024
#define NN 4096            // 4*UU gate columns (interleaved n' = 4u+g)
#define KK (II + UU)       // 1088 (warmup), decode K = UU = 1024
// ---------------- tiling ----------------
#define MT  128            // M tile (batch rows per CTA)
#define NTL 256            // N tile (gate cols per CTA) = 64 units
#define KC  64             // K chunk per stage (128B rows, SW128)
#define NTHR 512           // 16 warps, warp grid 4(M) x 4(N), warp tile 32x64
#define ZS_STRIDE 260      // z SMEM row stride (floats)

typedef __half f16;
typedef unsigned int u32;

// ---------------- device state (no allocation allowed) ----------------
__device__ f16 g_Wt_hi[NN * KK];        // warmup W^T, gate-interleaved, K-major
__device__ f16 g_Wt_lo[NN * KK];
__device__ f16 g_W2_hi[NN * UU];        // decode W'^T = (Wr + Wd@Wk)^T interleaved
__device__ f16 g_W2_lo[NN * UU];
__device__ float g_b2[NN];              // b' = b + bd@Wk (gate-major)
__device__ f16 g_x[Bx * TT * II];       // inputs, fp16
__device__ f16 g_h[2 * Bx * UU];        // double-buffered hidden state, fp16
__device__ float g_c[Bx * UU];

// ---------------- helpers ----------------
__device__ __forceinline__ u32 smem_u32(const void* p) {
    u32 a;
    asm("{ .reg .u64 t; cvta.to.shared.u64 t, %1; cvt.u32.u64 %0, t; }" : "=r"(a) : "l"(p));
    return a;
}
#define SWZ(o) ((o) ^ ((((u32)(o)) >> 3) & 0x70))

__device__ __forceinline__ void cp16(u32 dst, const void* src) {
    asm volatile("cp.async.cg.shared.global [%0], [%1], 16;\n" :: "r"(dst), "l"(src) : "memory");
}
__device__ __forceinline__ void cp_commit() {
    asm volatile("cp.async.commit_group;\n" ::: "memory");
}
template<int N> __device__ __forceinline__ void cp_wait() {
    asm volatile("cp.async.wait_group %0;\n" :: "n"(N) : "memory");
}
__device__ __forceinline__ void ldsm4(u32* r, u32 addr) {
    asm volatile("ldmatrix.sync.aligned.m8n8.x4.shared.b16 {%0,%1,%2,%3}, [%4];"
                 : "=r"(r[0]), "=r"(r[1]), "=r"(r[2]), "=r"(r[3]) : "r"(addr));
}
__device__ __forceinline__ void mma16816(float* c, const u32* a, const u32* b) {
    asm volatile("mma.sync.aligned.m16n8k16.row.col.f32.f16.f16.f32 "
                 "{%0,%1,%2,%3}, {%4,%5,%6,%7}, {%8,%9}, {%0,%1,%2,%3};"
                 : "+f"(c[0]), "+f"(c[1]), "+f"(c[2]), "+f"(c[3])
                 : "r"(a[0]), "r"(a[1]), "r"(a[2]), "r"(a[3]), "r"(b[0]), "r"(b[1]));
}
// fast sigmoid/tanh via MUFU (error ~ulp scale, negligible vs fp16 quant noise)
__device__ __forceinline__ float sigm(float z) {
    return __fdividef(1.0f, 1.0f + __expf(-z));
}
__device__ __forceinline__ float tanhfast(float z) {
    return __fdividef(2.0f, 1.0f + __expf(-2.0f * z)) - 1.0f;
}

// ---------------- prep kernels (once per launch) ----------------
__global__ void prep_weights(const float* __restrict__ Wk, const float* __restrict__ Wr) {
    const int np = blockIdx.x;               // n' = 4u+g
    const int u = np >> 2, g = np & 3;
    const int col = g * UU + u;
    for (int k = threadIdx.x; k < KK; k += blockDim.x) {
        float w = (k < II) ? Wk[(size_t)k * NN + col] : Wr[(size_t)(k - II) * NN + col];
        f16 hi = __float2half_rn(w);
        g_Wt_hi[(size_t)np * KK + k] = hi;
        g_Wt_lo[(size_t)np * KK + k] = __float2half_rn(w - __half2float(hi));
    }
}
// Decode W'^T = (Wr + Wd@Wk)^T and b' = b + bd@Wk.
__global__ void prep_w2(const float* __restrict__ Wk, const float* __restrict__ Wr,
                        const float* __restrict__ Wd, const float* __restrict__ b,
                        const float* __restrict__ bd) {
    __shared__ float wkcol[II];
    const int np = blockIdx.x;
    const int u = np >> 2, g = np & 3;
    const int col = g * UU + u;
    if (threadIdx.x < II) wkcol[threadIdx.x] = Wk[(size_t)threadIdx.x * NN + col];
    __syncthreads();
    for (int k = threadIdx.x; k < UU; k += blockDim.x) {
        float w = Wr[(size_t)k * NN + col];
        #pragma unroll 16
        for (int i = 0; i < II; i++) w += Wd[(size_t)k * II + i] * wkcol[i];
        f16 hi = __float2half_rn(w);
        g_W2_hi[(size_t)np * UU + k] = hi;
        g_W2_lo[(size_t)np * UU + k] = __float2half_rn(w - __half2float(hi));
    }
    if (threadIdx.x == 0) {
        float bb = b[col];
        for (int i = 0; i < II; i++) bb += bd[i] * wkcol[i];
        g_b2[col] = bb;
    }
}
__global__ void prep_inputs(const float* __restrict__ x) {
    size_t i = (size_t)blockIdx.x * blockDim.x + threadIdx.x;
    if (i >= (size_t)Bx * TT * II) return;
    g_x[i] = __float2half_rn(x[i]);
}

// ---------------- LSTM step via mma.sync (HMMA), fp16 2-term ----------------
// grid (16, 8) = 128 CTAs. 512 thr = 16 warps, warp grid 4(M) x 4(N), tile 32x64.
// z = A*Bh + A*Bl (A fp16, B split fp16 hi/lo), fp32 accum.
// Pipeline: ONE barrier per stage — cp_wait -> sync -> issue next -> compute.
__global__ __launch_bounds__(NTHR, 1)
void lstm_step_mma(const f16* __restrict__ xp, int x_ld, int first_is_x,
                   const f16* __restrict__ hp,
                   const f16* __restrict__ wth, const f16* __restrict__ wtl, int wt_k,
                   f16* __restrict__ op,
                   float* __restrict__ c, const float* __restrict__ bias, int nstg)
{
    extern __shared__ char dynsmem[];
    __shared__ float s_bias[NTL];

    char* smg = dynsmem + ((1024 - ((uintptr_t)dynsmem & 1023)) & 1023);
    const u32 base = smem_u32(smg);

    const int tid  = threadIdx.x;
    const int wid  = tid >> 5;
    const int lane = tid & 31;
    const int ni = blockIdx.x, mi = blockIdx.y;
    const int b0 = mi * MT;
    const int n0 = ni * NTL;
    const int u0 = ni * 64;
    const int wm = (wid >> 2) * 32;          // warp M offset (4 x 32 = 128)
    const int wn = (wid & 3) * 64;           // warp N offset (4 x 64 = 256)

    // stage buffers: per buf 80KB = A(16K) Bh(32K) Bl(32K)
    #define AT(bf)    (base + (bf) * 81920u)
    #define BT(bf, p) (base + (bf) * 81920u + 16384u + (p) * 32768u)

    if (tid < NTL) s_bias[tid] = bias[(tid & 3) * UU + u0 + (tid >> 2)];

    float acc[2][8][4];
    #pragma unroll
    for (int m = 0; m < 2; m++)
        #pragma unroll
        for (int n = 0; n < 8; n++)
            #pragma unroll
            for (int q = 0; q < 4; q++) acc[m][n][q] = 0.0f;

    auto issue_loads = [&](int s, int buf) {
        const int kg = s * KC;
        const f16* A; int lda, ka;
        if (first_is_x && s == 0) { A = xp; lda = x_ld; ka = 0; }
        else { A = hp; lda = UU; ka = kg - (first_is_x ? II : 0); }
        #pragma unroll
        for (int i = 0; i < 2; i++) {            // A: 1024 chunks / 512 thr
            int idx = tid + i * NTHR;
            int row = idx >> 3, q = idx & 7;
            cp16(AT(buf) + SWZ(row * 128 + q * 16),
                 A + (size_t)(b0 + row) * lda + ka + q * 8);
        }
        #pragma unroll
        for (int p = 0; p < 2; p++) {
            const f16* src = p ? wtl : wth;
            #pragma unroll
            for (int i = 0; i < 4; i++) {        // B: 2048 chunks per part / 512
                int idx = tid + i * NTHR;
                int row = idx >> 3, q = idx & 7;
                cp16(BT(buf, p) + SWZ(row * 128 + q * 16),
                     src + (size_t)(n0 + row) * wt_k + kg + q * 8);
            }
        }
        cp_commit();
    };

    issue_loads(0, 0);

    for (int t = 0; t < nstg; t++) {
        const int buf = t & 1;
        // 1) this thread's pending group (stage t's loads) done
        cp_wait<0>();
        // 2) ALL threads past their wait -> tile t fully visible; and all
        //    threads finished computing stage t-1 (program order) -> buf^1 free
        __syncthreads();
        // 3) prefetch stage t+1 into buf^1; overlaps the whole compute below
        if (t + 1 < nstg) issue_loads(t + 1, buf ^ 1);

        #pragma unroll
        for (int kk = 0; kk < 4; kk++) {
            // A: 2 x m16k16 fragments
            u32 ah[2][4];
            #pragma unroll
            for (int m = 0; m < 2; m++) {
                int row = wm + m * 16 + (lane & 15);
                ldsm4(ah[m], AT(buf) + SWZ(row * 128 + kk * 32 + (lane >> 4) * 16));
            }
            // B-hi: 8 x n8k16 fragments (pairs via x4)
            u32 bh[8][2];
            #pragma unroll
            for (int nf = 0; nf < 8; nf += 2) {
                int n = wn + nf * 8 + (lane >> 4) * 8 + (lane & 7);
                u32 r[4];
                ldsm4(r, BT(buf, 0) + SWZ(n * 128 + kk * 32 + ((lane >> 3) & 1) * 16));
                bh[nf][0] = r[0]; bh[nf][1] = r[1];
                bh[nf + 1][0] = r[2]; bh[nf + 1][1] = r[3];
            }
            #pragma unroll
            for (int m = 0; m < 2; m++)
                #pragma unroll
                for (int n = 0; n < 8; n++) mma16816(acc[m][n], ah[m], bh[n]);

            // A * B-lo (streamed)
            #pragma unroll
            for (int nf = 0; nf < 8; nf += 2) {
                int n = wn + nf * 8 + (lane >> 4) * 8 + (lane & 7);
                u32 r[4];
                ldsm4(r, BT(buf, 1) + SWZ(n * 128 + kk * 32 + ((lane >> 3) & 1) * 16));
                u32 b0f[2] = { r[0], r[1] }, b1f[2] = { r[2], r[3] };
                #pragma unroll
                for (int m = 0; m < 2; m++) {
                    mma16816(acc[m][nf],     ah[m], b0f);
                    mma16816(acc[m][nf + 1], ah[m], b1f);
                }
            }
        }
        // no trailing barrier: next iteration's cp_wait + sync covers the hazard
    }
    __syncthreads();   // all compute done before zs overwrites stage buffers

    // ---------------- epilogue: accums -> SMEM -> gate math -> c,h ----------------
    float* zs = (float*)smg;   // 128 x ZS_STRIDE fp32, reuses stage bufs
    #pragma unroll
    for (int m = 0; m < 2; m++) {
        int row = wm + m * 16 + (lane >> 2);
        #pragma unroll
        for (int n = 0; n < 8; n++) {
            int col = wn + n * 8 + (lane & 3) * 2;
            *(float2*)&zs[row * ZS_STRIDE + col]       = make_float2(acc[m][n][0], acc[m][n][1]);
            *(float2*)&zs[(row + 8) * ZS_STRIDE + col] = make_float2(acc[m][n][2], acc[m][n][3]);
        }
    }
    __syncthreads();

    #pragma unroll 1
    for (int it = 0; it < (MT * 64) / NTHR; it++) {    // 16 iterations
        int idx = tid + it * NTHR;
        int row = idx >> 6;
        int ul  = idx & 63;
        float4 z = *(const float4*)&zs[row * ZS_STRIDE + 4 * ul];
        float zi = z.x + s_bias[4 * ul + 0];
        float zf = z.y + s_bias[4 * ul + 1];
        float zg = z.z + s_bias[4 * ul + 2];
        float zo = z.w + s_bias[4 * ul + 3];

        const size_t gidx = (size_t)(b0 + row) * UU + u0 + ul;
        float cv = c[gidx];
        float cn = sigm(zf) * cv + sigm(zi) * tanhfast(zg);
        c[gidx] = cn;
        op[gidx] = __float2half_rn(sigm(zo) * tanhfast(cn));
    }
    #undef AT
    #undef BT
}

// ---------------- output kernel: only the indexed columns of pred ----------------
__global__ __launch_bounds__(256) void out_kernel(
    const f16* __restrict__ hp,
    const float* __restrict__ Wd, const float* __restrict__ bd,
    const int* __restrict__ oidx, int n_idx,
    float* __restrict__ out, int s, int S)
{
    const int wid  = threadIdx.x >> 5;
    const int lane = threadIdx.x & 31;
    const int b = blockIdx.x * 8 + wid;

    float a0 = 0.0f, a1 = 0.0f;                       // n_idx <= 2 fast path
    const int o0 = oidx[0];
    const int o1 = (n_idx > 1) ? oidx[1] : 0;
    #pragma unroll 4
    for (int i = 0; i < UU / 32; i++) {
        int u = lane + i * 32;
        float hv = __half2float(hp[(size_t)b * UU + u]);
        a0 += hv * Wd[(size_t)u * II + o0];
        a1 += hv * Wd[(size_t)u * II + o1];
    }
    #pragma unroll
    for (int off = 16; off > 0; off >>= 1) {
        a0 += __shfl_down_sync(0xFFFFFFFFu, a0, off);
        a1 += __shfl_down_sync(0xFFFFFFFFu, a1, off);
    }
    if (lane == 0) {
        out[((size_t)b * S + s) * n_idx + 0] = a0 + bd[o0];
        if (n_idx > 1) out[((size_t)b * S + s) * n_idx + 1] = a1 + bd[o1];
    }
}

// ---------------- host driver ----------------
extern "C" void kernel_launch(void* const* d_in, const int* in_sizes, int n_in,
                              void* d_out, int out_size)
{
    const float* inputs = (const float*)d_in[0];
    const float* Wk     = (const float*)d_in[1];
    const float* Wr     = (const float*)d_in[2];
    const float* bias   = (const float*)d_in[3];
    const float* Wd     = (const float*)d_in[4];
    const float* bd     = (const float*)d_in[5];
    const int*   oidx   = (const int*)d_in[6];
    float*       out    = (float*)d_out;

    const int n_idx = in_sizes[6];
    const int S     = out_size / (Bx * n_idx);

    f16 *xp, *hb, *wth, *wtl, *w2h, *w2l;
    float *cb, *b2;
    cudaGetSymbolAddress((void**)&xp, g_x);
    cudaGetSymbolAddress((void**)&hb, g_h);
    cudaGetSymbolAddress((void**)&cb, g_c);
    cudaGetSymbolAddress((void**)&wth, g_Wt_hi);
    cudaGetSymbolAddress((void**)&wtl, g_Wt_lo);
    cudaGetSymbolAddress((void**)&w2h, g_W2_hi);
    cudaGetSymbolAddress((void**)&w2l, g_W2_lo);
    cudaGetSymbolAddress((void**)&b2, g_b2);

    const int dyn_smem = 2 * 81920 + 1024;   // 164864 B
    cudaFuncSetAttribute(lstm_step_mma, cudaFuncAttributeMaxDynamicSharedMemorySize, dyn_smem);

    // one-time-per-launch prep
    prep_weights<<<NN, 256>>>(Wk, Wr);
    prep_w2<<<NN, 256>>>(Wk, Wr, Wd, bias, bd);
    prep_inputs<<<(Bx * TT * II) / 256, 256>>>(inputs);
    cudaMemsetAsync(hb, 0, sizeof(f16) * Bx * UU);   // zero buffer 0 only
    cudaMemsetAsync(cb, 0, sizeof(float) * Bx * UU);

    const dim3 grid(NN / NTL, Bx / MT);      // (16, 8) = 128 CTAs, single wave
    int cur = 0;

    // warmup: 256 steps, K = 1088 (x chunk + h)
    for (int t = 0; t < TT; t++) {
        lstm_step_mma<<<grid, NTHR, dyn_smem>>>(
            xp + (size_t)t * II, TT * II, 1,
            hb + (size_t)cur * Bx * UU,
            wth, wtl, KK,
            hb + (size_t)(cur ^ 1) * Bx * UU,
            cb, bias, KK / KC);
        cur ^= 1;
    }

    out_kernel<<<Bx / 8, 256>>>(hb + (size_t)cur * Bx * UU, Wd, bd, oidx, n_idx, out, 0, S);

    // decode: folded weights W' = Wr + Wd@Wk, K = 1024, no feedback kernel
    for (int s = 1; s < S; s++) {
        lstm_step_mma<<<grid, NTHR, dyn_smem>>>(
            (const f16*)0, 0, 0,
            hb + (size_t)cur * Bx * UU,
            w2h, w2l, UU,
            hb + (size_t)(cur ^ 1) * Bx * UU,
            cb, b2, UU / KC);
        cur ^= 1;
        out_kernel<<<Bx / 8, 256>>>(hb + (size_t)cur * Bx * UU, Wd, bd, oidx, n_idx, out, s, S);
    }
}

// round 11
// speedup vs baseline: 1.3469x; 1.0166x over previous
#include <cuda_runtime.h>
#include <cuda_fp16.h>
#include <cstdint>
#include <math.h>

// ---------------- problem dims (fixed by dataset) ----------------
#define Bx 1024
#define TT 256
#define II 64
#define UU 1024
#define NN 4096            // 4*UU gate columns (interleaved n' = 4u+g)
#define KK (II + UU)       // 1088 (warmup), decode K = UU = 1024
// ---------------- tiling ----------------
#define MT  128            // M tile (batch rows per CTA)
#define NTL 256            // N tile (gate cols per CTA) = 64 units
#define KC  64             // K chunk per stage (128B rows, SW128)
#define NTHR 512           // 16 warps, warp grid 4(M) x 4(N), warp tile 32x64
#define ZS_STRIDE 260      // z SMEM row stride (floats)

typedef __half f16;
typedef unsigned int u32;

// ---------------- device state (no allocation allowed) ----------------
__device__ f16 g_Wt_hi[NN * KK];        // warmup W^T, gate-interleaved, K-major
__device__ f16 g_Wt_lo[NN * KK];
__device__ f16 g_W2_hi[NN * UU];        // decode W'^T = (Wr + Wd@Wk)^T interleaved
__device__ f16 g_W2_lo[NN * UU];
__device__ float g_b2[NN];              // b' = b + bd@Wk (gate-major)
__device__ f16 g_x[Bx * TT * II];       // inputs, fp16
__device__ f16 g_h[2 * Bx * UU];        // double-buffered hidden state, fp16
__device__ float g_c[Bx * UU];

// ---------------- helpers ----------------
__device__ __forceinline__ u32 smem_u32(const void* p) {
    u32 a;
    asm("{ .reg .u64 t; cvta.to.shared.u64 t, %1; cvt.u32.u64 %0, t; }" : "=r"(a) : "l"(p));
    return a;
}
#define SWZ(o) ((o) ^ ((((u32)(o)) >> 3) & 0x70))

__device__ __forceinline__ void cp16(u32 dst, const void* src) {
    asm volatile("cp.async.cg.shared.global [%0], [%1], 16;\n" :: "r"(dst), "l"(src) : "memory");
}
__device__ __forceinline__ void cp_commit() {
    asm volatile("cp.async.commit_group;\n" ::: "memory");
}
template<int N> __device__ __forceinline__ void cp_wait() {
    asm volatile("cp.async.wait_group %0;\n" :: "n"(N) : "memory");
}
__device__ __forceinline__ void ldsm4(u32* r, u32 addr) {
    asm volatile("ldmatrix.sync.aligned.m8n8.x4.shared.b16 {%0,%1,%2,%3}, [%4];"
                 : "=r"(r[0]), "=r"(r[1]), "=r"(r[2]), "=r"(r[3]) : "r"(addr));
}
__device__ __forceinline__ void mma16816(float* c, const u32* a, const u32* b) {
    asm volatile("mma.sync.aligned.m16n8k16.row.col.f32.f16.f16.f32 "
                 "{%0,%1,%2,%3}, {%4,%5,%6,%7}, {%8,%9}, {%0,%1,%2,%3};"
                 : "+f"(c[0]), "+f"(c[1]), "+f"(c[2]), "+f"(c[3])
                 : "r"(a[0]), "r"(a[1]), "r"(a[2]), "r"(a[3]), "r"(b[0]), "r"(b[1]));
}
// fast sigmoid/tanh via MUFU (error ~ulp scale, negligible vs fp16 quant noise)
__device__ __forceinline__ float sigm(float z) {
    return __fdividef(1.0f, 1.0f + __expf(-z));
}
__device__ __forceinline__ float tanhfast(float z) {
    return __fdividef(2.0f, 1.0f + __expf(-2.0f * z)) - 1.0f;
}

// ---------------- prep kernels (once per launch) ----------------
__global__ void prep_weights(const float* __restrict__ Wk, const float* __restrict__ Wr) {
    const int np = blockIdx.x;               // n' = 4u+g
    const int u = np >> 2, g = np & 3;
    const int col = g * UU + u;
    for (int k = threadIdx.x; k < KK; k += blockDim.x) {
        float w = (k < II) ? Wk[(size_t)k * NN + col] : Wr[(size_t)(k - II) * NN + col];
        f16 hi = __float2half_rn(w);
        g_Wt_hi[(size_t)np * KK + k] = hi;
        g_Wt_lo[(size_t)np * KK + k] = __float2half_rn(w - __half2float(hi));
    }
}
// Decode W'^T = (Wr + Wd@Wk)^T and b' = b + bd@Wk.
__global__ void prep_w2(const float* __restrict__ Wk, const float* __restrict__ Wr,
                        const float* __restrict__ Wd, const float* __restrict__ b,
                        const float* __restrict__ bd) {
    __shared__ float wkcol[II];
    const int np = blockIdx.x;
    const int u = np >> 2, g = np & 3;
    const int col = g * UU + u;
    if (threadIdx.x < II) wkcol[threadIdx.x] = Wk[(size_t)threadIdx.x * NN + col];
    __syncthreads();
    for (int k = threadIdx.x; k < UU; k += blockDim.x) {
        float w = Wr[(size_t)k * NN + col];
        #pragma unroll 16
        for (int i = 0; i < II; i++) w += Wd[(size_t)k * II + i] * wkcol[i];
        f16 hi = __float2half_rn(w);
        g_W2_hi[(size_t)np * UU + k] = hi;
        g_W2_lo[(size_t)np * UU + k] = __float2half_rn(w - __half2float(hi));
    }
    if (threadIdx.x == 0) {
        float bb = b[col];
        for (int i = 0; i < II; i++) bb += bd[i] * wkcol[i];
        g_b2[col] = bb;
    }
}
__global__ void prep_inputs(const float* __restrict__ x) {
    size_t i = (size_t)blockIdx.x * blockDim.x + threadIdx.x;
    if (i >= (size_t)Bx * TT * II) return;
    g_x[i] = __float2half_rn(x[i]);
}

// ---------------- LSTM step via mma.sync (HMMA), fp16 2-term ----------------
// grid (16, 8) = 128 CTAs. 512 thr = 16 warps, warp grid 4(M) x 4(N), tile 32x64.
// z = A*Bh + A*Bl (A fp16, B split fp16 hi/lo), fp32 accum.
// Pipeline: one barrier per stage (cp_wait -> sync -> issue next -> compute),
// A-fragment double-buffered across kk to keep LDSMs in flight under the MMAs.
// skip_lo0: warmup drops the lo term for the x stage (64/1088 K, err +~6e-5).
// out_s >= 0 (decode): warps 0-7 emit out[out_s] for 8 rows from the INPUT h,
// overlapped with the stage-0 cp.async wait (thin + spread, unlike R9's fused col).
__global__ __launch_bounds__(NTHR, 1)
void lstm_step_mma(const f16* __restrict__ xp, int x_ld, int first_is_x, int skip_lo0,
                   const f16* __restrict__ hp,
                   const f16* __restrict__ wth, const f16* __restrict__ wtl, int wt_k,
                   f16* __restrict__ op,
                   float* __restrict__ c, const float* __restrict__ bias, int nstg,
                   const float* __restrict__ Wd, const float* __restrict__ bd,
                   const int* __restrict__ oidx, int n_idx,
                   float* __restrict__ out, int out_s, int S)
{
    extern __shared__ char dynsmem[];
    __shared__ float s_bias[NTL];

    char* smg = dynsmem + ((1024 - ((uintptr_t)dynsmem & 1023)) & 1023);
    const u32 base = smem_u32(smg);

    const int tid  = threadIdx.x;
    const int wid  = tid >> 5;
    const int lane = tid & 31;
    const int ni = blockIdx.x, mi = blockIdx.y;
    const int b0 = mi * MT;
    const int n0 = ni * NTL;
    const int u0 = ni * 64;
    const int wm = (wid >> 2) * 32;          // warp M offset (4 x 32 = 128)
    const int wn = (wid & 3) * 64;           // warp N offset (4 x 64 = 256)

    // stage buffers: per buf 80KB = A(16K) Bh(32K) Bl(32K)
    #define AT(bf)    (base + (bf) * 81920u)
    #define BT(bf, p) (base + (bf) * 81920u + 16384u + (p) * 32768u)

    if (tid < NTL) s_bias[tid] = bias[(tid & 3) * UU + u0 + (tid >> 2)];

    float acc[2][8][4];
    #pragma unroll
    for (int m = 0; m < 2; m++)
        #pragma unroll
        for (int n = 0; n < 8; n++)
            #pragma unroll
            for (int q = 0; q < 4; q++) acc[m][n][q] = 0.0f;

    auto issue_loads = [&](int s, int buf) {
        const int kg = s * KC;
        const f16* A; int lda, ka;
        if (first_is_x && s == 0) { A = xp; lda = x_ld; ka = 0; }
        else { A = hp; lda = UU; ka = kg - (first_is_x ? II : 0); }
        #pragma unroll
        for (int i = 0; i < 2; i++) {            // A: 1024 chunks / 512 thr
            int idx = tid + i * NTHR;
            int row = idx >> 3, q = idx & 7;
            cp16(AT(buf) + SWZ(row * 128 + q * 16),
                 A + (size_t)(b0 + row) * lda + ka + q * 8);
        }
        const int pmax = (skip_lo0 && s == 0) ? 1 : 2;   // skip Bl for x stage
        for (int p = 0; p < pmax; p++) {
            const f16* src = p ? wtl : wth;
            #pragma unroll
            for (int i = 0; i < 4; i++) {        // B: 2048 chunks per part / 512
                int idx = tid + i * NTHR;
                int row = idx >> 3, q = idx & 7;
                cp16(BT(buf, p) + SWZ(row * 128 + q * 16),
                     src + (size_t)(n0 + row) * wt_k + kg + q * 8);
            }
        }
        cp_commit();
    };

    issue_loads(0, 0);

    // ---- thin fused output head (decode only): 8 rows per CTA, warps 0-7,
    // overlapped with the stage-0 cp.async transfer.
    if (out_s >= 0 && wid < 8) {
        const int row = b0 + ni * 8 + wid;       // 128 CTAs x 8 rows = 1024
        const int o0 = oidx[0];
        const int o1 = (n_idx > 1) ? oidx[1] : o0;
        float a0 = 0.0f, a1 = 0.0f;
        #pragma unroll 4
        for (int i = 0; i < UU / 32; i++) {
            int u = lane + i * 32;
            float hv = __half2float(hp[(size_t)row * UU + u]);
            a0 += hv * Wd[(size_t)u * II + o0];
            a1 += hv * Wd[(size_t)u * II + o1];
        }
        #pragma unroll
        for (int off = 16; off > 0; off >>= 1) {
            a0 += __shfl_down_sync(0xFFFFFFFFu, a0, off);
            a1 += __shfl_down_sync(0xFFFFFFFFu, a1, off);
        }
        if (lane == 0) {
            out[((size_t)row * S + out_s) * n_idx + 0] = a0 + bd[o0];
            if (n_idx > 1) out[((size_t)row * S + out_s) * n_idx + 1] = a1 + bd[o1];
        }
    }

    for (int t = 0; t < nstg; t++) {
        const int buf = t & 1;
        cp_wait<0>();          // stage t's loads (this thread's last group) done
        __syncthreads();       // tile visible to all; buf^1's readers all done
        if (t + 1 < nstg) issue_loads(t + 1, buf ^ 1);   // overlaps compute below

        const bool do_lo = !(skip_lo0 && first_is_x && t == 0);

        // A fragments double-buffered across kk
        u32 ah[2][2][4];
        #pragma unroll
        for (int m = 0; m < 2; m++) {
            int row = wm + m * 16 + (lane & 15);
            ldsm4(ah[0][m], AT(buf) + SWZ(row * 128 + 0 + (lane >> 4) * 16));
        }

        #pragma unroll
        for (int kk = 0; kk < 4; kk++) {
            const int cb = kk & 1, nb = cb ^ 1;
            // B-hi: 8 x n8k16 fragments (pairs via x4)
            u32 bh[8][2];
            #pragma unroll
            for (int nf = 0; nf < 8; nf += 2) {
                int n = wn + nf * 8 + (lane >> 4) * 8 + (lane & 7);
                u32 r[4];
                ldsm4(r, BT(buf, 0) + SWZ(n * 128 + kk * 32 + ((lane >> 3) & 1) * 16));
                bh[nf][0] = r[0]; bh[nf][1] = r[1];
                bh[nf + 1][0] = r[2]; bh[nf + 1][1] = r[3];
            }
            // prefetch next kk's A fragments under the MMAs below
            if (kk < 3) {
                #pragma unroll
                for (int m = 0; m < 2; m++) {
                    int row = wm + m * 16 + (lane & 15);
                    ldsm4(ah[nb][m], AT(buf) + SWZ(row * 128 + (kk + 1) * 32 + (lane >> 4) * 16));
                }
            }
            #pragma unroll
            for (int m = 0; m < 2; m++)
                #pragma unroll
                for (int n = 0; n < 8; n++) mma16816(acc[m][n], ah[cb][m], bh[n]);

            // A * B-lo (streamed)
            if (do_lo) {
                #pragma unroll
                for (int nf = 0; nf < 8; nf += 2) {
                    int n = wn + nf * 8 + (lane >> 4) * 8 + (lane & 7);
                    u32 r[4];
                    ldsm4(r, BT(buf, 1) + SWZ(n * 128 + kk * 32 + ((lane >> 3) & 1) * 16));
                    u32 b0f[2] = { r[0], r[1] }, b1f[2] = { r[2], r[3] };
                    #pragma unroll
                    for (int m = 0; m < 2; m++) {
                        mma16816(acc[m][nf],     ah[cb][m], b0f);
                        mma16816(acc[m][nf + 1], ah[cb][m], b1f);
                    }
                }
            }
        }
        // no trailing barrier: next iteration's cp_wait + sync covers the hazard
    }
    __syncthreads();   // all compute done before zs overwrites stage buffers

    // ---------------- epilogue: accums -> SMEM -> gate math -> c,h ----------------
    float* zs = (float*)smg;   // 128 x ZS_STRIDE fp32, reuses stage bufs
    #pragma unroll
    for (int m = 0; m < 2; m++) {
        int row = wm + m * 16 + (lane >> 2);
        #pragma unroll
        for (int n = 0; n < 8; n++) {
            int col = wn + n * 8 + (lane & 3) * 2;
            *(float2*)&zs[row * ZS_STRIDE + col]       = make_float2(acc[m][n][0], acc[m][n][1]);
            *(float2*)&zs[(row + 8) * ZS_STRIDE + col] = make_float2(acc[m][n][2], acc[m][n][3]);
        }
    }
    __syncthreads();

    #pragma unroll 1
    for (int it = 0; it < (MT * 64) / NTHR; it++) {    // 16 iterations
        int idx = tid + it * NTHR;
        int row = idx >> 6;
        int ul  = idx & 63;
        float4 z = *(const float4*)&zs[row * ZS_STRIDE + 4 * ul];
        float zi = z.x + s_bias[4 * ul + 0];
        float zf = z.y + s_bias[4 * ul + 1];
        float zg = z.z + s_bias[4 * ul + 2];
        float zo = z.w + s_bias[4 * ul + 3];

        const size_t gidx = (size_t)(b0 + row) * UU + u0 + ul;
        float cv = c[gidx];
        float cn = sigm(zf) * cv + sigm(zi) * tanhfast(zg);
        c[gidx] = cn;
        op[gidx] = __float2half_rn(sigm(zo) * tanhfast(cn));
    }
    #undef AT
    #undef BT
}

// ---------------- standalone output kernel (final step only) ----------------
__global__ __launch_bounds__(256) void out_kernel(
    const f16* __restrict__ hp,
    const float* __restrict__ Wd, const float* __restrict__ bd,
    const int* __restrict__ oidx, int n_idx,
    float* __restrict__ out, int s, int S)
{
    const int wid  = threadIdx.x >> 5;
    const int lane = threadIdx.x & 31;
    const int b = blockIdx.x * 8 + wid;

    float a0 = 0.0f, a1 = 0.0f;                       // n_idx <= 2 fast path
    const int o0 = oidx[0];
    const int o1 = (n_idx > 1) ? oidx[1] : 0;
    #pragma unroll 4
    for (int i = 0; i < UU / 32; i++) {
        int u = lane + i * 32;
        float hv = __half2float(hp[(size_t)b * UU + u]);
        a0 += hv * Wd[(size_t)u * II + o0];
        a1 += hv * Wd[(size_t)u * II + o1];
    }
    #pragma unroll
    for (int off = 16; off > 0; off >>= 1) {
        a0 += __shfl_down_sync(0xFFFFFFFFu, a0, off);
        a1 += __shfl_down_sync(0xFFFFFFFFu, a1, off);
    }
    if (lane == 0) {
        out[((size_t)b * S + s) * n_idx + 0] = a0 + bd[o0];
        if (n_idx > 1) out[((size_t)b * S + s) * n_idx + 1] = a1 + bd[o1];
    }
}

// ---------------- host driver ----------------
extern "C" void kernel_launch(void* const* d_in, const int* in_sizes, int n_in,
                              void* d_out, int out_size)
{
    const float* inputs = (const float*)d_in[0];
    const float* Wk     = (const float*)d_in[1];
    const float* Wr     = (const float*)d_in[2];
    const float* bias   = (const float*)d_in[3];
    const float* Wd     = (const float*)d_in[4];
    const float* bd     = (const float*)d_in[5];
    const int*   oidx   = (const int*)d_in[6];
    float*       out    = (float*)d_out;

    const int n_idx = in_sizes[6];
    const int S     = out_size / (Bx * n_idx);

    f16 *xp, *hb, *wth, *wtl, *w2h, *w2l;
    float *cb, *b2;
    cudaGetSymbolAddress((void**)&xp, g_x);
    cudaGetSymbolAddress((void**)&hb, g_h);
    cudaGetSymbolAddress((void**)&cb, g_c);
    cudaGetSymbolAddress((void**)&wth, g_Wt_hi);
    cudaGetSymbolAddress((void**)&wtl, g_Wt_lo);
    cudaGetSymbolAddress((void**)&w2h, g_W2_hi);
    cudaGetSymbolAddress((void**)&w2l, g_W2_lo);
    cudaGetSymbolAddress((void**)&b2, g_b2);

    const int dyn_smem = 2 * 81920 + 1024;   // 164864 B
    cudaFuncSetAttribute(lstm_step_mma, cudaFuncAttributeMaxDynamicSharedMemorySize, dyn_smem);

    // one-time-per-launch prep
    prep_weights<<<NN, 256>>>(Wk, Wr);
    prep_w2<<<NN, 256>>>(Wk, Wr, Wd, bias, bd);
    prep_inputs<<<(Bx * TT * II) / 256, 256>>>(inputs);
    cudaMemsetAsync(hb, 0, sizeof(f16) * Bx * UU);   // zero buffer 0 only
    cudaMemsetAsync(cb, 0, sizeof(float) * Bx * UU);

    const dim3 grid(NN / NTL, Bx / MT);      // (16, 8) = 128 CTAs, single wave
    int cur = 0;

    // warmup: 256 steps, K = 1088 (x chunk + h); x stage runs hi-only
    for (int t = 0; t < TT; t++) {
        lstm_step_mma<<<grid, NTHR, dyn_smem>>>(
            xp + (size_t)t * II, TT * II, 1, 1,
            hb + (size_t)cur * Bx * UU,
            wth, wtl, KK,
            hb + (size_t)(cur ^ 1) * Bx * UU,
            cb, bias, KK / KC,
            Wd, bd, oidx, n_idx, out, -1, S);
        cur ^= 1;
    }

    // decode: folded weights W' = Wr + Wd@Wk, K = 1024; each step also emits
    // out[s-1] from its input h via the thin fused head.
    for (int s = 1; s < S; s++) {
        lstm_step_mma<<<grid, NTHR, dyn_smem>>>(
            (const f16*)0, 0, 0, 0,
            hb + (size_t)cur * Bx * UU,
            w2h, w2l, UU,
            hb + (size_t)(cur ^ 1) * Bx * UU,
            cb, b2, UU / KC,
            Wd, bd, oidx, n_idx, out, s - 1, S);
        cur ^= 1;
    }

    // final step's output
    out_kernel<<<Bx / 8, 256>>>(hb + (size_t)cur * Bx * UU, Wd, bd, oidx, n_idx,
                                out, S - 1, S);
}

// round 12
// speedup vs baseline: 1.3501x; 1.0024x over previous
#include <cuda_runtime.h>
#include <cuda_fp16.h>
#include <cstdint>
#include <math.h>

// ---------------- problem dims (fixed by dataset) ----------------
#define Bx 1024
#define TT 256
#define II 64
#define UU 1024
#define NN 4096            // 4*UU gate columns (interleaved n' = 4u+g)
#define KK (II + UU)       // 1088 (warmup), decode K = UU = 1024
// ---------------- tiling ----------------
#define MT  128            // M tile (batch rows per CTA)
#define NTL 128            // N tile (gate cols per CTA) = 32 units
#define KC  64             // K chunk per stage (128B rows, SW128)
#define NTHR 256           // 8 warps, warp grid 4(M) x 2(N), warp tile 32x64
#define ZS_STRIDE 132      // z SMEM row stride (floats)

typedef __half f16;
typedef unsigned int u32;

// ---------------- device state (no allocation allowed) ----------------
__device__ f16 g_Wt_hi[NN * KK];        // warmup W^T, gate-interleaved, K-major
__device__ f16 g_Wt_lo[NN * KK];
__device__ f16 g_W2_hi[NN * UU];        // decode W'^T = (Wr + Wd@Wk)^T interleaved
__device__ f16 g_W2_lo[NN * UU];
__device__ float g_b2[NN];              // b' = b + bd@Wk (gate-major)
__device__ f16 g_x[Bx * TT * II];       // inputs, fp16
__device__ f16 g_h[2 * Bx * UU];        // double-buffered hidden state, fp16
__device__ float g_c[Bx * UU];

// ---------------- helpers ----------------
__device__ __forceinline__ u32 smem_u32(const void* p) {
    u32 a;
    asm("{ .reg .u64 t; cvta.to.shared.u64 t, %1; cvt.u32.u64 %0, t; }" : "=r"(a) : "l"(p));
    return a;
}
#define SWZ(o) ((o) ^ ((((u32)(o)) >> 3) & 0x70))

__device__ __forceinline__ void cp16(u32 dst, const void* src) {
    asm volatile("cp.async.cg.shared.global [%0], [%1], 16;\n" :: "r"(dst), "l"(src) : "memory");
}
__device__ __forceinline__ void cp_commit() {
    asm volatile("cp.async.commit_group;\n" ::: "memory");
}
template<int N> __device__ __forceinline__ void cp_wait() {
    asm volatile("cp.async.wait_group %0;\n" :: "n"(N) : "memory");
}
__device__ __forceinline__ void ldsm4(u32* r, u32 addr) {
    asm volatile("ldmatrix.sync.aligned.m8n8.x4.shared.b16 {%0,%1,%2,%3}, [%4];"
                 : "=r"(r[0]), "=r"(r[1]), "=r"(r[2]), "=r"(r[3]) : "r"(addr));
}
__device__ __forceinline__ void mma16816(float* c, const u32* a, const u32* b) {
    asm volatile("mma.sync.aligned.m16n8k16.row.col.f32.f16.f16.f32 "
                 "{%0,%1,%2,%3}, {%4,%5,%6,%7}, {%8,%9}, {%0,%1,%2,%3};"
                 : "+f"(c[0]), "+f"(c[1]), "+f"(c[2]), "+f"(c[3])
                 : "r"(a[0]), "r"(a[1]), "r"(a[2]), "r"(a[3]), "r"(b[0]), "r"(b[1]));
}
// fast sigmoid/tanh via MUFU (error ~ulp scale, negligible vs fp16 quant noise)
__device__ __forceinline__ float sigm(float z) {
    return __fdividef(1.0f, 1.0f + __expf(-z));
}
__device__ __forceinline__ float tanhfast(float z) {
    return __fdividef(2.0f, 1.0f + __expf(-2.0f * z)) - 1.0f;
}

// ---------------- prep kernels (once per launch) ----------------
__global__ void prep_weights(const float* __restrict__ Wk, const float* __restrict__ Wr) {
    const int np = blockIdx.x;               // n' = 4u+g
    const int u = np >> 2, g = np & 3;
    const int col = g * UU + u;
    for (int k = threadIdx.x; k < KK; k += blockDim.x) {
        float w = (k < II) ? Wk[(size_t)k * NN + col] : Wr[(size_t)(k - II) * NN + col];
        f16 hi = __float2half_rn(w);
        g_Wt_hi[(size_t)np * KK + k] = hi;
        g_Wt_lo[(size_t)np * KK + k] = __float2half_rn(w - __half2float(hi));
    }
}
// Decode W'^T = (Wr + Wd@Wk)^T and b' = b + bd@Wk.
__global__ void prep_w2(const float* __restrict__ Wk, const float* __restrict__ Wr,
                        const float* __restrict__ Wd, const float* __restrict__ b,
                        const float* __restrict__ bd) {
    __shared__ float wkcol[II];
    const int np = blockIdx.x;
    const int u = np >> 2, g = np & 3;
    const int col = g * UU + u;
    if (threadIdx.x < II) wkcol[threadIdx.x] = Wk[(size_t)threadIdx.x * NN + col];
    __syncthreads();
    for (int k = threadIdx.x; k < UU; k += blockDim.x) {
        float w = Wr[(size_t)k * NN + col];
        #pragma unroll 16
        for (int i = 0; i < II; i++) w += Wd[(size_t)k * II + i] * wkcol[i];
        f16 hi = __float2half_rn(w);
        g_W2_hi[(size_t)np * UU + k] = hi;
        g_W2_lo[(size_t)np * UU + k] = __float2half_rn(w - __half2float(hi));
    }
    if (threadIdx.x == 0) {
        float bb = b[col];
        for (int i = 0; i < II; i++) bb += bd[i] * wkcol[i];
        g_b2[col] = bb;
    }
}
__global__ void prep_inputs(const float* __restrict__ x) {
    size_t i = (size_t)blockIdx.x * blockDim.x + threadIdx.x;
    if (i >= (size_t)Bx * TT * II) return;
    g_x[i] = __float2half_rn(x[i]);
}

// ---------------- LSTM step via mma.sync (HMMA), fp16 2-term ----------------
// grid (32, 8) = 256 CTAs, 2 CTAs/SM (the point: a CTA's cp_wait/barrier/epilogue
// overlaps the co-resident CTA's MMAs). 256 thr = 8 warps, warp grid 4(M) x 2(N),
// warp tile 32x64 (same inner-loop shape as before).
// z = A*Bh + A*Bl (A fp16, B split fp16 hi/lo), fp32 accum.
// skip_lo0: warmup drops the lo term for the x stage (64/1088 K, err +~6e-5).
// out_s >= 0 (decode): warps 0-3 emit out[out_s] for 4 rows from the INPUT h,
// overlapped with the stage-0 cp.async transfer.
__global__ __launch_bounds__(NTHR, 2)
void lstm_step_mma(const f16* __restrict__ xp, int x_ld, int first_is_x, int skip_lo0,
                   const f16* __restrict__ hp,
                   const f16* __restrict__ wth, const f16* __restrict__ wtl, int wt_k,
                   f16* __restrict__ op,
                   float* __restrict__ c, const float* __restrict__ bias, int nstg,
                   const float* __restrict__ Wd, const float* __restrict__ bd,
                   const int* __restrict__ oidx, int n_idx,
                   float* __restrict__ out, int out_s, int S)
{
    extern __shared__ char dynsmem[];
    __shared__ float s_bias[NTL];

    char* smg = dynsmem + ((1024 - ((uintptr_t)dynsmem & 1023)) & 1023);
    const u32 base = smem_u32(smg);

    const int tid  = threadIdx.x;
    const int wid  = tid >> 5;
    const int lane = tid & 31;
    const int ni = blockIdx.x, mi = blockIdx.y;
    const int b0 = mi * MT;
    const int n0 = ni * NTL;
    const int u0 = ni * 32;
    const int wm = (wid >> 1) * 32;          // warp M offset (4 x 32 = 128)
    const int wn = (wid & 1) * 64;           // warp N offset (2 x 64 = 128)

    // stage buffers: per buf 48KB = A(16K) Bh(16K) Bl(16K)
    #define AT(bf)    (base + (bf) * 49152u)
    #define BT(bf, p) (base + (bf) * 49152u + 16384u + (p) * 16384u)

    if (tid < NTL) s_bias[tid] = bias[(tid & 3) * UU + u0 + (tid >> 2)];

    float acc[2][8][4];
    #pragma unroll
    for (int m = 0; m < 2; m++)
        #pragma unroll
        for (int n = 0; n < 8; n++)
            #pragma unroll
            for (int q = 0; q < 4; q++) acc[m][n][q] = 0.0f;

    auto issue_loads = [&](int s, int buf) {
        const int kg = s * KC;
        const f16* A; int lda, ka;
        if (first_is_x && s == 0) { A = xp; lda = x_ld; ka = 0; }
        else { A = hp; lda = UU; ka = kg - (first_is_x ? II : 0); }
        #pragma unroll
        for (int i = 0; i < 4; i++) {            // A: 1024 chunks / 256 thr
            int idx = tid + i * NTHR;
            int row = idx >> 3, q = idx & 7;
            cp16(AT(buf) + SWZ(row * 128 + q * 16),
                 A + (size_t)(b0 + row) * lda + ka + q * 8);
        }
        const int pmax = (skip_lo0 && s == 0) ? 1 : 2;   // skip Bl for x stage
        for (int p = 0; p < pmax; p++) {
            const f16* src = p ? wtl : wth;
            #pragma unroll
            for (int i = 0; i < 4; i++) {        // B: 1024 chunks per part / 256
                int idx = tid + i * NTHR;
                int row = idx >> 3, q = idx & 7;
                cp16(BT(buf, p) + SWZ(row * 128 + q * 16),
                     src + (size_t)(n0 + row) * wt_k + kg + q * 8);
            }
        }
        cp_commit();
    };

    issue_loads(0, 0);

    // ---- thin fused output head (decode only): 4 rows per CTA, warps 0-3,
    // overlapped with the stage-0 cp.async transfer.
    if (out_s >= 0 && wid < 4) {
        const int row = b0 + ni * 4 + wid;       // 256 CTAs x 4 rows = 1024
        const int o0 = oidx[0];
        const int o1 = (n_idx > 1) ? oidx[1] : o0;
        float a0 = 0.0f, a1 = 0.0f;
        #pragma unroll 4
        for (int i = 0; i < UU / 32; i++) {
            int u = lane + i * 32;
            float hv = __half2float(hp[(size_t)row * UU + u]);
            a0 += hv * Wd[(size_t)u * II + o0];
            a1 += hv * Wd[(size_t)u * II + o1];
        }
        #pragma unroll
        for (int off = 16; off > 0; off >>= 1) {
            a0 += __shfl_down_sync(0xFFFFFFFFu, a0, off);
            a1 += __shfl_down_sync(0xFFFFFFFFu, a1, off);
        }
        if (lane == 0) {
            out[((size_t)row * S + out_s) * n_idx + 0] = a0 + bd[o0];
            if (n_idx > 1) out[((size_t)row * S + out_s) * n_idx + 1] = a1 + bd[o1];
        }
    }

    for (int t = 0; t < nstg; t++) {
        const int buf = t & 1;
        cp_wait<0>();          // stage t's loads (this thread's last group) done
        __syncthreads();       // tile visible to all; buf^1's readers all done
        if (t + 1 < nstg) issue_loads(t + 1, buf ^ 1);   // overlaps compute below

        const bool do_lo = !(skip_lo0 && first_is_x && t == 0);

        // A fragments double-buffered across kk
        u32 ah[2][2][4];
        #pragma unroll
        for (int m = 0; m < 2; m++) {
            int row = wm + m * 16 + (lane & 15);
            ldsm4(ah[0][m], AT(buf) + SWZ(row * 128 + 0 + (lane >> 4) * 16));
        }

        #pragma unroll
        for (int kk = 0; kk < 4; kk++) {
            const int cb = kk & 1, nb = cb ^ 1;
            // B-hi: 8 x n8k16 fragments (pairs via x4)
            u32 bh[8][2];
            #pragma unroll
            for (int nf = 0; nf < 8; nf += 2) {
                int n = wn + nf * 8 + (lane >> 4) * 8 + (lane & 7);
                u32 r[4];
                ldsm4(r, BT(buf, 0) + SWZ(n * 128 + kk * 32 + ((lane >> 3) & 1) * 16));
                bh[nf][0] = r[0]; bh[nf][1] = r[1];
                bh[nf + 1][0] = r[2]; bh[nf + 1][1] = r[3];
            }
            // prefetch next kk's A fragments under the MMAs below
            if (kk < 3) {
                #pragma unroll
                for (int m = 0; m < 2; m++) {
                    int row = wm + m * 16 + (lane & 15);
                    ldsm4(ah[nb][m], AT(buf) + SWZ(row * 128 + (kk + 1) * 32 + (lane >> 4) * 16));
                }
            }
            #pragma unroll
            for (int m = 0; m < 2; m++)
                #pragma unroll
                for (int n = 0; n < 8; n++) mma16816(acc[m][n], ah[cb][m], bh[n]);

            // A * B-lo (streamed)
            if (do_lo) {
                #pragma unroll
                for (int nf = 0; nf < 8; nf += 2) {
                    int n = wn + nf * 8 + (lane >> 4) * 8 + (lane & 7);
                    u32 r[4];
                    ldsm4(r, BT(buf, 1) + SWZ(n * 128 + kk * 32 + ((lane >> 3) & 1) * 16));
                    u32 b0f[2] = { r[0], r[1] }, b1f[2] = { r[2], r[3] };
                    #pragma unroll
                    for (int m = 0; m < 2; m++) {
                        mma16816(acc[m][nf],     ah[cb][m], b0f);
                        mma16816(acc[m][nf + 1], ah[cb][m], b1f);
                    }
                }
            }
        }
        // no trailing barrier: next iteration's cp_wait + sync covers the hazard
    }
    __syncthreads();   // all compute done before zs overwrites stage buffers

    // ---------------- epilogue: accums -> SMEM -> gate math -> c,h ----------------
    float* zs = (float*)smg;   // 128 x ZS_STRIDE fp32 (67.6KB), reuses stage bufs
    #pragma unroll
    for (int m = 0; m < 2; m++) {
        int row = wm + m * 16 + (lane >> 2);
        #pragma unroll
        for (int n = 0; n < 8; n++) {
            int col = wn + n * 8 + (lane & 3) * 2;
            *(float2*)&zs[row * ZS_STRIDE + col]       = make_float2(acc[m][n][0], acc[m][n][1]);
            *(float2*)&zs[(row + 8) * ZS_STRIDE + col] = make_float2(acc[m][n][2], acc[m][n][3]);
        }
    }
    __syncthreads();

    #pragma unroll 1
    for (int it = 0; it < (MT * 32) / NTHR; it++) {    // 16 iterations
        int idx = tid + it * NTHR;
        int row = idx >> 5;            // 0..127
        int ul  = idx & 31;            // unit within tile
        float4 z = *(const float4*)&zs[row * ZS_STRIDE + 4 * ul];
        float zi = z.x + s_bias[4 * ul + 0];
        float zf = z.y + s_bias[4 * ul + 1];
        float zg = z.z + s_bias[4 * ul + 2];
        float zo = z.w + s_bias[4 * ul + 3];

        const size_t gidx = (size_t)(b0 + row) * UU + u0 + ul;
        float cv = c[gidx];
        float cn = sigm(zf) * cv + sigm(zi) * tanhfast(zg);
        c[gidx] = cn;
        op[gidx] = __float2half_rn(sigm(zo) * tanhfast(cn));
    }
    #undef AT
    #undef BT
}

// ---------------- standalone output kernel (final step only) ----------------
__global__ __launch_bounds__(256) void out_kernel(
    const f16* __restrict__ hp,
    const float* __restrict__ Wd, const float* __restrict__ bd,
    const int* __restrict__ oidx, int n_idx,
    float* __restrict__ out, int s, int S)
{
    const int wid  = threadIdx.x >> 5;
    const int lane = threadIdx.x & 31;
    const int b = blockIdx.x * 8 + wid;

    float a0 = 0.0f, a1 = 0.0f;                       // n_idx <= 2 fast path
    const int o0 = oidx[0];
    const int o1 = (n_idx > 1) ? oidx[1] : 0;
    #pragma unroll 4
    for (int i = 0; i < UU / 32; i++) {
        int u = lane + i * 32;
        float hv = __half2float(hp[(size_t)b * UU + u]);
        a0 += hv * Wd[(size_t)u * II + o0];
        a1 += hv * Wd[(size_t)u * II + o1];
    }
    #pragma unroll
    for (int off = 16; off > 0; off >>= 1) {
        a0 += __shfl_down_sync(0xFFFFFFFFu, a0, off);
        a1 += __shfl_down_sync(0xFFFFFFFFu, a1, off);
    }
    if (lane == 0) {
        out[((size_t)b * S + s) * n_idx + 0] = a0 + bd[o0];
        if (n_idx > 1) out[((size_t)b * S + s) * n_idx + 1] = a1 + bd[o1];
    }
}

// ---------------- host driver ----------------
extern "C" void kernel_launch(void* const* d_in, const int* in_sizes, int n_in,
                              void* d_out, int out_size)
{
    const float* inputs = (const float*)d_in[0];
    const float* Wk     = (const float*)d_in[1];
    const float* Wr     = (const float*)d_in[2];
    const float* bias   = (const float*)d_in[3];
    const float* Wd     = (const float*)d_in[4];
    const float* bd     = (const float*)d_in[5];
    const int*   oidx   = (const int*)d_in[6];
    float*       out    = (float*)d_out;

    const int n_idx = in_sizes[6];
    const int S     = out_size / (Bx * n_idx);

    f16 *xp, *hb, *wth, *wtl, *w2h, *w2l;
    float *cb, *b2;
    cudaGetSymbolAddress((void**)&xp, g_x);
    cudaGetSymbolAddress((void**)&hb, g_h);
    cudaGetSymbolAddress((void**)&cb, g_c);
    cudaGetSymbolAddress((void**)&wth, g_Wt_hi);
    cudaGetSymbolAddress((void**)&wtl, g_Wt_lo);
    cudaGetSymbolAddress((void**)&w2h, g_W2_hi);
    cudaGetSymbolAddress((void**)&w2l, g_W2_lo);
    cudaGetSymbolAddress((void**)&b2, g_b2);

    const int dyn_smem = 2 * 49152 + 1024;   // 99328 B -> 2 CTAs/SM
    cudaFuncSetAttribute(lstm_step_mma, cudaFuncAttributeMaxDynamicSharedMemorySize, dyn_smem);

    // one-time-per-launch prep
    prep_weights<<<NN, 256>>>(Wk, Wr);
    prep_w2<<<NN, 256>>>(Wk, Wr, Wd, bias, bd);
    prep_inputs<<<(Bx * TT * II) / 256, 256>>>(inputs);
    cudaMemsetAsync(hb, 0, sizeof(f16) * Bx * UU);   // zero buffer 0 only
    cudaMemsetAsync(cb, 0, sizeof(float) * Bx * UU);

    const dim3 grid(NN / NTL, Bx / MT);      // (32, 8) = 256 CTAs, one wave @ 2/SM
    int cur = 0;

    // warmup: 256 steps, K = 1088 (x chunk + h); x stage runs hi-only
    for (int t = 0; t < TT; t++) {
        lstm_step_mma<<<grid, NTHR, dyn_smem>>>(
            xp + (size_t)t * II, TT * II, 1, 1,
            hb + (size_t)cur * Bx * UU,
            wth, wtl, KK,
            hb + (size_t)(cur ^ 1) * Bx * UU,
            cb, bias, KK / KC,
            Wd, bd, oidx, n_idx, out, -1, S);
        cur ^= 1;
    }

    // decode: folded weights W' = Wr + Wd@Wk, K = 1024; each step also emits
    // out[s-1] from its input h via the thin fused head.
    for (int s = 1; s < S; s++) {
        lstm_step_mma<<<grid, NTHR, dyn_smem>>>(
            (const f16*)0, 0, 0, 0,
            hb + (size_t)cur * Bx * UU,
            w2h, w2l, UU,
            hb + (size_t)(cur ^ 1) * Bx * UU,
            cb, b2, UU / KC,
            Wd, bd, oidx, n_idx, out, s - 1, S);
        cur ^= 1;
    }

    // final step's output
    out_kernel<<<Bx / 8, 256>>>(hb + (size_t)cur * Bx * UU, Wd, bd, oidx, n_idx,
                                out, S - 1, S);
}